// round 15
// baseline (speedup 1.0000x reference)
#include <cuda_runtime.h>
#include <cstdint>

#define HDIM 2048
#define NTOK 8192          // B*S
#define NTHREADS 256
#define NCTAS 456          // 152 SMs * 3 resident CTAs
#define CHUNK 1024         // NTHREADS * 4 floats
#define EPSV 1e-6f

__device__ __forceinline__ float4 ldcs4(const float* p) {
    float4 v;
    asm volatile("ld.global.cs.v4.f32 {%0,%1,%2,%3}, [%4];"
                 : "=f"(v.x), "=f"(v.y), "=f"(v.z), "=f"(v.w) : "l"(p));
    return v;
}
__device__ __forceinline__ void stcs4(float* p, float4 v) {
    asm volatile("st.global.cs.v4.f32 [%0], {%1,%2,%3,%4};"
                 :: "l"(p), "f"(v.x), "f"(v.y), "f"(v.z), "f"(v.w));
}
__device__ __forceinline__ float tanh_fast(float x) {
    float y; asm("tanh.approx.f32 %0, %1;" : "=f"(y) : "f"(x)); return y;
}
__device__ __forceinline__ float dot4(float4 a, float4 b) {
    return a.x*b.x + a.y*b.y + a.z*b.z + a.w*b.w;
}

__global__ __launch_bounds__(NTHREADS, 3)
void altup_v11_kernel(const float* __restrict__ hs,     // [4, NTOK, H]
                      const float* __restrict__ act,    // [NTOK, H]
                      const float* __restrict__ w,      // [H]
                      const float* __restrict__ rw,     // [4, H]
                      const float* __restrict__ pw,     // [16, 4]
                      const float* __restrict__ cw,     // [4, 4]
                      const float* __restrict__ oscale, // [H]
                      float* __restrict__ out)          // [4, NTOK, H]
{
    const int tid = threadIdx.x;
    const int warp = tid >> 5, lane = tid & 31;
    const float inv_h = 1.0f / (float)HDIM;

    __shared__ float q_s[4][HDIM];     // fused router weights (32 KB)
    __shared__ float red[2][8][10];    // ping-pong partials, 8 warps
    __shared__ float pw_s[64];
    __shared__ float cw_s[16];

    // ---- one-time staging: q = w * rw (each thread fills 2 chunks/row) ----
    #pragma unroll
    for (int r = 0; r < 4; r++) {
        #pragma unroll
        for (int c = 0; c < 2; c++) {
            int h = tid*4 + c*CHUNK;
            float4 wv = __ldg((const float4*)(w + h));
            float4 rv = __ldg((const float4*)(rw + r*HDIM + h));
            *(float4*)&q_s[r][h] = make_float4(wv.x*rv.x, wv.y*rv.y, wv.z*rv.z, wv.w*rv.w);
        }
    }
    if (tid < 64) pw_s[tid] = pw[tid];
    if (tid < 16) cw_s[tid] = cw[tid];
    float4 sv[2];
    sv[0] = __ldg((const float4*)(oscale + tid*4));
    sv[1] = __ldg((const float4*)(oscale + tid*4 + CHUNK));
    __syncthreads();

    int par = 0;
    for (int t = blockIdx.x; t < NTOK; t += NCTAS, par ^= 1) {
        const size_t base = (size_t)t * HDIM;
        // ---- stream loads: 10 LDG.128 in flight per thread ----
        float4 x0[2], av[2], x1[2], x2[2], x3[2];
        #pragma unroll
        for (int c = 0; c < 2; c++) {
            const int h = tid*4 + c*CHUNK;
            x0[c] = ldcs4(hs  + base + h);
            av[c] = ldcs4(act + base + h);
            x1[c] = ldcs4(hs + (size_t)1*NTOK*HDIM + base + h);
            x2[c] = ldcs4(hs + (size_t)2*NTOK*HDIM + base + h);
            x3[c] = ldcs4(hs + (size_t)3*NTOK*HDIM + base + h);
        }

        // ---- dots against smem-resident fused weights ----
        float p[10];
        #pragma unroll
        for (int k = 0; k < 10; k++) p[k] = 0.f;
        #pragma unroll
        for (int c = 0; c < 2; c++) {
            const int h = tid*4 + c*CHUNK;
            p[0] += dot4(x0[c], x0[c]);
            p[5] += dot4(av[c], av[c]);
            {
                float4 q0 = *(const float4*)&q_s[0][h];
                float4 q1 = *(const float4*)&q_s[1][h];
                p[1] += dot4(x0[c], q0);  p[2] += dot4(x0[c], q1);
                p[6] += dot4(av[c], q0);  p[7] += dot4(av[c], q1);
            }
            {
                float4 q2 = *(const float4*)&q_s[2][h];
                float4 q3 = *(const float4*)&q_s[3][h];
                p[3] += dot4(x0[c], q2);  p[4] += dot4(x0[c], q3);
                p[8] += dot4(av[c], q2);  p[9] += dot4(av[c], q3);
            }
        }

        // ---- warp shuffle reduce, write partials, ONE barrier ----
        #pragma unroll
        for (int k = 0; k < 10; k++) {
            #pragma unroll
            for (int o = 16; o > 0; o >>= 1)
                p[k] += __shfl_xor_sync(0xffffffffu, p[k], o);
        }
        if (lane == 0) {
            #pragma unroll
            for (int k = 0; k < 10; k++) red[par][warp][k] = p[k];
        }
        __syncthreads();

        // ---- EVERY warp independently: finalize sums + coef math ----
        float f = 0.f;
        if (lane < 10) {
            #pragma unroll
            for (int wi = 0; wi < 8; wi++) f += red[par][wi][lane];
        }
        float fin[10];
        #pragma unroll
        for (int k = 0; k < 10; k++)
            fin[k] = __shfl_sync(0xffffffffu, f, k);

        float g0 = rsqrtf(fin[0] * inv_h + EPSV) * inv_h;
        float g1 = rsqrtf(fin[5] * inv_h + EPSV) * inv_h;

        // lanes 0..15: c[j][i] (lane = j*4+i); lanes 16..19: cc[lane-16]
        float cf;
        if (lane < 16) {
            float s = 0.f;
            #pragma unroll
            for (int n = 0; n < 4; n++)
                s = fmaf(tanh_fast(fin[1 + n] * g0), pw_s[lane*4 + n], s);
            cf = s;
        } else {
            int n = lane & 3;
            float s = 1.0f;
            #pragma unroll
            for (int k = 0; k < 4; k++)
                s = fmaf(tanh_fast(fin[6 + k] * g1), cw_s[n*4 + k], s);
            cf = s;
        }

        // ---- phase 2: per row j, shuffle 5 coefs once, apply to both chunks ----
        float innov[2][4];
        {
            const float c0  = __shfl_sync(0xffffffffu, cf, 0);
            const float c1  = __shfl_sync(0xffffffffu, cf, 1);
            const float c2  = __shfl_sync(0xffffffffu, cf, 2);
            const float c3  = __shfl_sync(0xffffffffu, cf, 3);
            const float cc0 = __shfl_sync(0xffffffffu, cf, 16);
            #pragma unroll
            for (int c = 0; c < 2; c++) {
                const int h = tid*4 + c*CHUNK;
                const float xr[4][4] = {
                    {x0[c].x, x0[c].y, x0[c].z, x0[c].w},
                    {x1[c].x, x1[c].y, x1[c].z, x1[c].w},
                    {x2[c].x, x2[c].y, x2[c].z, x2[c].w},
                    {x3[c].x, x3[c].y, x3[c].z, x3[c].w}};
                const float ar[4] = {av[c].x, av[c].y, av[c].z, av[c].w};
                const float sr[4] = {sv[c].x, sv[c].y, sv[c].z, sv[c].w};
                float4 o4; float* op = &o4.x;
                #pragma unroll
                for (int comp = 0; comp < 4; comp++) {
                    float s = xr[0][comp];
                    s = fmaf(c0, xr[0][comp], s);
                    s = fmaf(c1, xr[1][comp], s);
                    s = fmaf(c2, xr[2][comp], s);
                    s = fmaf(c3, xr[3][comp], s);
                    innov[c][comp] = ar[comp] - s;
                    op[comp] = (s + innov[c][comp]*cc0) * sr[comp];
                }
                stcs4(out + base + h, o4);
            }
        }
        #pragma unroll
        for (int j = 1; j < 4; j++) {
            const float c0  = __shfl_sync(0xffffffffu, cf, j*4 + 0);
            const float c1  = __shfl_sync(0xffffffffu, cf, j*4 + 1);
            const float c2  = __shfl_sync(0xffffffffu, cf, j*4 + 2);
            const float c3  = __shfl_sync(0xffffffffu, cf, j*4 + 3);
            const float ccj = __shfl_sync(0xffffffffu, cf, 16 + j);
            #pragma unroll
            for (int c = 0; c < 2; c++) {
                const int h = tid*4 + c*CHUNK;
                const float xr[4][4] = {
                    {x0[c].x, x0[c].y, x0[c].z, x0[c].w},
                    {x1[c].x, x1[c].y, x1[c].z, x1[c].w},
                    {x2[c].x, x2[c].y, x2[c].z, x2[c].w},
                    {x3[c].x, x3[c].y, x3[c].z, x3[c].w}};
                const float sr[4] = {sv[c].x, sv[c].y, sv[c].z, sv[c].w};
                float4 o4; float* op = &o4.x;
                #pragma unroll
                for (int comp = 0; comp < 4; comp++) {
                    float s = xr[j][comp];
                    s = fmaf(c0, xr[0][comp], s);
                    s = fmaf(c1, xr[1][comp], s);
                    s = fmaf(c2, xr[2][comp], s);
                    s = fmaf(c3, xr[3][comp], s);
                    op[comp] = (s + innov[c][comp]*ccj) * sr[comp];
                }
                stcs4(out + (size_t)j*NTOK*HDIM + base + h, o4);
            }
        }
        // no trailing barrier: red ping-pongs by parity; same-parity reuse is
        // separated by the single barrier of the intervening iteration.
    }
}

extern "C" void kernel_launch(void* const* d_in, const int* in_sizes, int n_in,
                              void* d_out, int out_size)
{
    const float* hs     = (const float*)d_in[0];
    const float* act    = (const float*)d_in[1];
    const float* w      = (const float*)d_in[2];
    const float* rw     = (const float*)d_in[3];
    const float* pw     = (const float*)d_in[4];
    const float* cw     = (const float*)d_in[5];
    const float* oscale = (const float*)d_in[6];
    float* out = (float*)d_out;

    altup_v11_kernel<<<NCTAS, NTHREADS>>>(hs, act, w, rw, pw, cw, oscale, out);
}

// round 16
// speedup vs baseline: 1.0581x; 1.0581x over previous
#include <cuda_runtime.h>
#include <cstdint>

#define HDIM 2048
#define NTOK 8192          // B*S
#define NTHREADS 256
#define NCTAS 608          // 152 SMs * 4 resident CTAs
#define CHUNK 1024         // NTHREADS * 4 floats
#define EPSV 1e-6f

__device__ __forceinline__ float4 ldcs4(const float* p) {
    float4 v;
    asm volatile("ld.global.cs.v4.f32 {%0,%1,%2,%3}, [%4];"
                 : "=f"(v.x), "=f"(v.y), "=f"(v.z), "=f"(v.w) : "l"(p));
    return v;
}
__device__ __forceinline__ void stcs4(float* p, float4 v) {
    asm volatile("st.global.cs.v4.f32 [%0], {%1,%2,%3,%4};"
                 :: "l"(p), "f"(v.x), "f"(v.y), "f"(v.z), "f"(v.w));
}
__device__ __forceinline__ float tanh_fast(float x) {
    float y; asm("tanh.approx.f32 %0, %1;" : "=f"(y) : "f"(x)); return y;
}
__device__ __forceinline__ float dot4(float4 a, float4 b) {
    return a.x*b.x + a.y*b.y + a.z*b.z + a.w*b.w;
}

__global__ __launch_bounds__(NTHREADS, 4)
void altup_v12_kernel(const float* __restrict__ hs,     // [4, NTOK, H]
                      const float* __restrict__ act,    // [NTOK, H]
                      const float* __restrict__ w,      // [H]
                      const float* __restrict__ rw,     // [4, H]
                      const float* __restrict__ pw,     // [16, 4]
                      const float* __restrict__ cw,     // [4, 4]
                      const float* __restrict__ oscale, // [H]
                      float* __restrict__ out)          // [4, NTOK, H]
{
    const int tid = threadIdx.x;
    const int warp = tid >> 5, lane = tid & 31;
    const int h0 = tid * 4, h1 = h0 + CHUNK;
    const float inv_h = 1.0f / (float)HDIM;

    __shared__ float q_s[4][HDIM];     // fused router weights (32 KB)
    __shared__ float red[2][8][10];    // ping-pong partials, 8 warps
    __shared__ float pw_s[64];
    __shared__ float cw_s[16];

    // ---- one-time staging: q = w * rw ----
    #pragma unroll
    for (int r = 0; r < 4; r++) {
        #pragma unroll
        for (int c = 0; c < 2; c++) {
            int h = h0 + c*CHUNK;
            float4 wv = __ldg((const float4*)(w + h));
            float4 rv = __ldg((const float4*)(rw + r*HDIM + h));
            *(float4*)&q_s[r][h] = make_float4(wv.x*rv.x, wv.y*rv.y, wv.z*rv.z, wv.w*rv.w);
        }
    }
    if (tid < 64) pw_s[tid] = pw[tid];
    if (tid < 16) cw_s[tid] = cw[tid];
    const float4 sv0 = __ldg((const float4*)(oscale + h0));
    const float4 sv1 = __ldg((const float4*)(oscale + h1));
    __syncthreads();

    int par = 0;
    for (int t = blockIdx.x; t < NTOK; t += NCTAS, par ^= 1) {
        const size_t base = (size_t)t * HDIM;

        // ---- pre-barrier loads: both chunks' x0/act + chunk-0 x1..x3 ----
        float4 x0a = ldcs4(hs  + base + h0);
        float4 ava = ldcs4(act + base + h0);
        float4 x0b = ldcs4(hs  + base + h1);
        float4 avb = ldcs4(act + base + h1);
        float4 x1a = ldcs4(hs + (size_t)1*NTOK*HDIM + base + h0);
        float4 x2a = ldcs4(hs + (size_t)2*NTOK*HDIM + base + h0);
        float4 x3a = ldcs4(hs + (size_t)3*NTOK*HDIM + base + h0);

        // ---- dots against smem-resident fused weights (both chunks) ----
        float p[10];
        p[0] = dot4(x0a, x0a) + dot4(x0b, x0b);
        p[5] = dot4(ava, ava) + dot4(avb, avb);
        {
            float4 qa = *(const float4*)&q_s[0][h0];
            float4 qb = *(const float4*)&q_s[0][h1];
            p[1] = dot4(x0a, qa) + dot4(x0b, qb);
            p[6] = dot4(ava, qa) + dot4(avb, qb);
        }
        {
            float4 qa = *(const float4*)&q_s[1][h0];
            float4 qb = *(const float4*)&q_s[1][h1];
            p[2] = dot4(x0a, qa) + dot4(x0b, qb);
            p[7] = dot4(ava, qa) + dot4(avb, qb);
        }
        {
            float4 qa = *(const float4*)&q_s[2][h0];
            float4 qb = *(const float4*)&q_s[2][h1];
            p[3] = dot4(x0a, qa) + dot4(x0b, qb);
            p[8] = dot4(ava, qa) + dot4(avb, qb);
        }
        {
            float4 qa = *(const float4*)&q_s[3][h0];
            float4 qb = *(const float4*)&q_s[3][h1];
            p[4] = dot4(x0a, qa) + dot4(x0b, qb);
            p[9] = dot4(ava, qa) + dot4(avb, qb);
        }

        // ---- warp shuffle reduce, write partials, ONE barrier ----
        #pragma unroll
        for (int k = 0; k < 10; k++) {
            #pragma unroll
            for (int o = 16; o > 0; o >>= 1)
                p[k] += __shfl_xor_sync(0xffffffffu, p[k], o);
        }
        if (lane == 0) {
            #pragma unroll
            for (int k = 0; k < 10; k++) red[par][warp][k] = p[k];
        }
        __syncthreads();

        // ---- deferred chunk-1 stream loads (latency hides under coef+phase2a) ----
        float4 x1b = ldcs4(hs + (size_t)1*NTOK*HDIM + base + h1);
        float4 x2b = ldcs4(hs + (size_t)2*NTOK*HDIM + base + h1);
        float4 x3b = ldcs4(hs + (size_t)3*NTOK*HDIM + base + h1);

        // ---- EVERY warp independently: finalize sums + coef math ----
        float f = 0.f;
        if (lane < 10) {
            #pragma unroll
            for (int wi = 0; wi < 8; wi++) f += red[par][wi][lane];
        }
        float fin[10];
        #pragma unroll
        for (int k = 0; k < 10; k++)
            fin[k] = __shfl_sync(0xffffffffu, f, k);

        float g0 = rsqrtf(fin[0] * inv_h + EPSV) * inv_h;
        float g1 = rsqrtf(fin[5] * inv_h + EPSV) * inv_h;

        float cf;
        if (lane < 16) {
            float s = 0.f;
            #pragma unroll
            for (int n = 0; n < 4; n++)
                s = fmaf(tanh_fast(fin[1 + n] * g0), pw_s[lane*4 + n], s);
            cf = s;
        } else {
            int n = lane & 3;
            float s = 1.0f;
            #pragma unroll
            for (int k = 0; k < 4; k++)
                s = fmaf(tanh_fast(fin[6 + k] * g1), cw_s[n*4 + k], s);
            cf = s;
        }

        // ---- phase 2: chunk 0 fully, then chunk 1 ----
        const float c00 = __shfl_sync(0xffffffffu, cf, 0);
        const float c01 = __shfl_sync(0xffffffffu, cf, 1);
        const float c02 = __shfl_sync(0xffffffffu, cf, 2);
        const float c03 = __shfl_sync(0xffffffffu, cf, 3);
        const float cc0 = __shfl_sync(0xffffffffu, cf, 16);

        float innovA[4], innovB[4];
        {   // chunk 0, row 0
            const float xr0[4] = {x0a.x, x0a.y, x0a.z, x0a.w};
            const float xr1[4] = {x1a.x, x1a.y, x1a.z, x1a.w};
            const float xr2[4] = {x2a.x, x2a.y, x2a.z, x2a.w};
            const float xr3[4] = {x3a.x, x3a.y, x3a.z, x3a.w};
            const float ar[4]  = {ava.x, ava.y, ava.z, ava.w};
            const float sr[4]  = {sv0.x, sv0.y, sv0.z, sv0.w};
            float4 o4; float* op = &o4.x;
            #pragma unroll
            for (int comp = 0; comp < 4; comp++) {
                float s = xr0[comp];
                s = fmaf(c00, xr0[comp], s);
                s = fmaf(c01, xr1[comp], s);
                s = fmaf(c02, xr2[comp], s);
                s = fmaf(c03, xr3[comp], s);
                innovA[comp] = ar[comp] - s;
                op[comp] = (s + innovA[comp]*cc0) * sr[comp];
            }
            stcs4(out + base + h0, o4);
        }
        #pragma unroll
        for (int j = 1; j < 4; j++) {   // chunk 0, rows 1..3
            const float c0  = __shfl_sync(0xffffffffu, cf, j*4 + 0);
            const float c1  = __shfl_sync(0xffffffffu, cf, j*4 + 1);
            const float c2  = __shfl_sync(0xffffffffu, cf, j*4 + 2);
            const float c3  = __shfl_sync(0xffffffffu, cf, j*4 + 3);
            const float ccj = __shfl_sync(0xffffffffu, cf, 16 + j);
            const float xr0[4] = {x0a.x, x0a.y, x0a.z, x0a.w};
            const float xr1[4] = {x1a.x, x1a.y, x1a.z, x1a.w};
            const float xr2[4] = {x2a.x, x2a.y, x2a.z, x2a.w};
            const float xr3[4] = {x3a.x, x3a.y, x3a.z, x3a.w};
            const float xj[4]  = {j==1?x1a.x:(j==2?x2a.x:x3a.x),
                                  j==1?x1a.y:(j==2?x2a.y:x3a.y),
                                  j==1?x1a.z:(j==2?x2a.z:x3a.z),
                                  j==1?x1a.w:(j==2?x2a.w:x3a.w)};
            const float sr[4]  = {sv0.x, sv0.y, sv0.z, sv0.w};
            float4 o4; float* op = &o4.x;
            #pragma unroll
            for (int comp = 0; comp < 4; comp++) {
                float s = xj[comp];
                s = fmaf(c0, xr0[comp], s);
                s = fmaf(c1, xr1[comp], s);
                s = fmaf(c2, xr2[comp], s);
                s = fmaf(c3, xr3[comp], s);
                op[comp] = (s + innovA[comp]*ccj) * sr[comp];
            }
            stcs4(out + (size_t)j*NTOK*HDIM + base + h0, o4);
        }
        {   // chunk 1, row 0
            const float xr0[4] = {x0b.x, x0b.y, x0b.z, x0b.w};
            const float xr1[4] = {x1b.x, x1b.y, x1b.z, x1b.w};
            const float xr2[4] = {x2b.x, x2b.y, x2b.z, x2b.w};
            const float xr3[4] = {x3b.x, x3b.y, x3b.z, x3b.w};
            const float ar[4]  = {avb.x, avb.y, avb.z, avb.w};
            const float sr[4]  = {sv1.x, sv1.y, sv1.z, sv1.w};
            float4 o4; float* op = &o4.x;
            #pragma unroll
            for (int comp = 0; comp < 4; comp++) {
                float s = xr0[comp];
                s = fmaf(c00, xr0[comp], s);
                s = fmaf(c01, xr1[comp], s);
                s = fmaf(c02, xr2[comp], s);
                s = fmaf(c03, xr3[comp], s);
                innovB[comp] = ar[comp] - s;
                op[comp] = (s + innovB[comp]*cc0) * sr[comp];
            }
            stcs4(out + base + h1, o4);
        }
        #pragma unroll
        for (int j = 1; j < 4; j++) {   // chunk 1, rows 1..3
            const float c0  = __shfl_sync(0xffffffffu, cf, j*4 + 0);
            const float c1  = __shfl_sync(0xffffffffu, cf, j*4 + 1);
            const float c2  = __shfl_sync(0xffffffffu, cf, j*4 + 2);
            const float c3  = __shfl_sync(0xffffffffu, cf, j*4 + 3);
            const float ccj = __shfl_sync(0xffffffffu, cf, 16 + j);
            const float xr0[4] = {x0b.x, x0b.y, x0b.z, x0b.w};
            const float xr1[4] = {x1b.x, x1b.y, x1b.z, x1b.w};
            const float xr2[4] = {x2b.x, x2b.y, x2b.z, x2b.w};
            const float xr3[4] = {x3b.x, x3b.y, x3b.z, x3b.w};
            const float xj[4]  = {j==1?x1b.x:(j==2?x2b.x:x3b.x),
                                  j==1?x1b.y:(j==2?x2b.y:x3b.y),
                                  j==1?x1b.z:(j==2?x2b.z:x3b.z),
                                  j==1?x1b.w:(j==2?x2b.w:x3b.w)};
            const float sr[4]  = {sv1.x, sv1.y, sv1.z, sv1.w};
            float4 o4; float* op = &o4.x;
            #pragma unroll
            for (int comp = 0; comp < 4; comp++) {
                float s = xj[comp];
                s = fmaf(c0, xr0[comp], s);
                s = fmaf(c1, xr1[comp], s);
                s = fmaf(c2, xr2[comp], s);
                s = fmaf(c3, xr3[comp], s);
                op[comp] = (s + innovB[comp]*ccj) * sr[comp];
            }
            stcs4(out + (size_t)j*NTOK*HDIM + base + h1, o4);
        }
        // no trailing barrier: red ping-pongs by parity.
    }
}

extern "C" void kernel_launch(void* const* d_in, const int* in_sizes, int n_in,
                              void* d_out, int out_size)
{
    const float* hs     = (const float*)d_in[0];
    const float* act    = (const float*)d_in[1];
    const float* w      = (const float*)d_in[2];
    const float* rw     = (const float*)d_in[3];
    const float* pw     = (const float*)d_in[4];
    const float* cw     = (const float*)d_in[5];
    const float* oscale = (const float*)d_in[6];
    float* out = (float*)d_out;

    altup_v12_kernel<<<NCTAS, NTHREADS>>>(hs, act, w, rw, pw, cw, oscale, out);
}